// round 13
// baseline (speedup 1.0000x reference)
#include <cuda_runtime.h>
#include <cuda_bf16.h>
#include <cstdint>

// Problem constants (fixed shapes)
#define NH    32
#define NKV   8
#define HD    128
#define S_LEN 2048
#define B_SZ  2
#define HID   4096
#define MROWS (B_SZ * S_LEN)   // 4096
#define NREP  (NH / NKV)       // 4

#define E16M (16u * 1024u * 1024u)
#define E4M  (4u  * 1024u * 1024u)
#define WQKV_E (6144u * 4096u)   // combined q|k|v weight rows

// ---------------------------------------------------------------------------
// Scratch (device globals; allocation-free per harness rules)
// ---------------------------------------------------------------------------
__device__ float g_q [(size_t)MROWS * NH  * HD];
__device__ float g_k [(size_t)MROWS * NKV * HD];

// bf16 hi/lo copies
__device__ __nv_bfloat16 g_hs_h[E16M],  g_hs_l[E16M];
__device__ __nv_bfloat16 g_w_h[WQKV_E], g_w_l[WQKV_E];   // wq|wk|wv combined
__device__ __nv_bfloat16 g_wo_h[E16M],  g_wo_l[E16M];
__device__ __nv_bfloat16 g_ao_h[E16M],  g_ao_l[E16M];
// post-rope bf16 hi/lo q/k, direct-split v for attention
__device__ __nv_bfloat16 g_q_h[E16M], g_q_l[E16M];
__device__ __nv_bfloat16 g_k_h[E4M],  g_k_l[E4M];
__device__ __nv_bfloat16 g_v_h[E4M],  g_v_l[E4M];

// ---------------------------------------------------------------------------
// Common helpers (sm_80-level PTX only; no 'a'-suffix features)
// ---------------------------------------------------------------------------
__device__ __forceinline__ uint32_t smem_u32(const void* p) {
    uint32_t a;
    asm("{ .reg .u64 t; cvta.to.shared.u64 t, %1; cvt.u32.u64 %0, t; }"
        : "=r"(a) : "l"(p));
    return a;
}
__device__ __forceinline__ uint32_t pack_bf16x2(float a, float b) {
    __nv_bfloat162 h = __floats2bfloat162_rn(a, b);
    return *reinterpret_cast<uint32_t*>(&h);
}
__device__ __forceinline__ void cp16(uint32_t saddr, const void* gptr) {
    asm volatile("cp.async.cg.shared.global [%0], [%1], 16;"
                 :: "r"(saddr), "l"(gptr));
}
__device__ __forceinline__ void cp_commit() {
    asm volatile("cp.async.commit_group;" ::: "memory");
}
template <int N>
__device__ __forceinline__ void cp_wait() {
    asm volatile("cp.async.wait_group %0;" :: "n"(N) : "memory");
}
// ldmatrix.x4 over macro-row layout: logical rows of 32 bf16 (64B) are packed
// in pairs into 128B macro-rows with the standard XOR-8 swizzle.
__device__ __forceinline__ void ldm_x4_k32(uint32_t* r, uint32_t base, int row0, int kt) {
    const int l  = (int)(threadIdx.x & 31);
    const int rr = row0 + (l & 15);
    const int kc = 2 * kt + (l >> 4);
    const int mr = rr >> 1;
    const int ch = (((rr & 1) << 2) | kc) ^ (mr & 7);
    const uint32_t addr = base + (uint32_t)(mr * 128 + ch * 16);
    asm volatile("ldmatrix.sync.aligned.m8n8.x4.shared.b16 {%0,%1,%2,%3}, [%4];"
                 : "=r"(r[0]), "=r"(r[1]), "=r"(r[2]), "=r"(r[3]) : "r"(addr));
}
// ldmatrix.x4, 256B-wide rows (attention tiles, HD=128 bf16 per row)
__device__ __forceinline__ void ldm_x4_256(uint32_t* r, uint32_t base, int row0, int c0) {
    const int l  = (int)(threadIdx.x & 31);
    const int rr = row0 + (l & 15);
    const int cc = (c0 + (l >> 4)) ^ (rr & 7);
    const uint32_t addr = base + (uint32_t)(rr * 256 + cc * 16);
    asm volatile("ldmatrix.sync.aligned.m8n8.x4.shared.b16 {%0,%1,%2,%3}, [%4];"
                 : "=r"(r[0]), "=r"(r[1]), "=r"(r[2]), "=r"(r[3]) : "r"(addr));
}
__device__ __forceinline__ void ldm_x4t_256(uint32_t* r, uint32_t base, int row0, int c0) {
    const int l  = (int)(threadIdx.x & 31);
    const int rr = row0 + (l & 15);
    const int cc = (c0 + (l >> 4)) ^ (rr & 7);
    const uint32_t addr = base + (uint32_t)(rr * 256 + cc * 16);
    asm volatile("ldmatrix.sync.aligned.m8n8.x4.trans.shared.b16 {%0,%1,%2,%3}, [%4];"
                 : "=r"(r[0]), "=r"(r[1]), "=r"(r[2]), "=r"(r[3]) : "r"(addr));
}
__device__ __forceinline__ void mma_bf16(float* d, const uint32_t* a,
                                         uint32_t b0, uint32_t b1) {
    asm volatile(
        "mma.sync.aligned.m16n8k16.row.col.f32.bf16.bf16.f32 "
        "{%0,%1,%2,%3}, {%4,%5,%6,%7}, {%8,%9}, {%0,%1,%2,%3};"
        : "+f"(d[0]), "+f"(d[1]), "+f"(d[2]), "+f"(d[3])
        : "r"(a[0]), "r"(a[1]), "r"(a[2]), "r"(a[3]), "r"(b0), "r"(b1));
}
__device__ __forceinline__ void pack_hilo(float p0, float p1, uint32_t& hi, uint32_t& lo) {
    float h0 = __bfloat162float(__float2bfloat16(p0));
    float h1 = __bfloat162float(__float2bfloat16(p1));
    hi = pack_bf16x2(h0, h1);
    lo = pack_bf16x2(p0 - h0, p1 - h1);
}

// ---------------------------------------------------------------------------
// Merged fp32 -> bf16 hi/lo conversion for all 5 inputs, one launch, MLP=8.
// ---------------------------------------------------------------------------
#define CVT_BLOCKS 7168

__global__ __launch_bounds__(256) void cvt_all_kernel(
    const float4* __restrict__ s0, uint2* __restrict__ h0, uint2* __restrict__ l0,
    const float4* __restrict__ s1, uint2* __restrict__ h1, uint2* __restrict__ l1,
    const float4* __restrict__ s2, uint2* __restrict__ h2, uint2* __restrict__ l2,
    const float4* __restrict__ s3, uint2* __restrict__ h3, uint2* __restrict__ l3,
    const float4* __restrict__ s4, uint2* __restrict__ h4, uint2* __restrict__ l4)
{
    const int blk = blockIdx.x;
    const float4* x; uint2* hi; uint2* lo; int base; int q;
    if (blk < 2048)      { x = s0; hi = h0; lo = l0; base = blk;        q = 524288; }
    else if (blk < 4096) { x = s1; hi = h1; lo = l1; base = blk - 2048; q = 524288; }
    else if (blk < 4608) { x = s2; hi = h2; lo = l2; base = blk - 4096; q = 131072; }
    else if (blk < 5120) { x = s3; hi = h3; lo = l3; base = blk - 4608; q = 131072; }
    else                 { x = s4; hi = h4; lo = l4; base = blk - 5120; q = 524288; }

    const int i = base * 256 + (int)threadIdx.x;
    float4 f[8];
#pragma unroll
    for (int u = 0; u < 8; u++) f[u] = x[i + u * q];   // 8 independent LDGs
#pragma unroll
    for (int u = 0; u < 8; u++) {
        float xs[4] = {f[u].x, f[u].y, f[u].z, f[u].w};
        float hf[4], lf[4];
#pragma unroll
        for (int t = 0; t < 4; t++) {
            __nv_bfloat16 h = __float2bfloat16(xs[t]);
            hf[t] = __bfloat162float(h);
            lf[t] = xs[t] - hf[t];
        }
        uint2 H, L;
        H.x = pack_bf16x2(hf[0], hf[1]); H.y = pack_bf16x2(hf[2], hf[3]);
        L.x = pack_bf16x2(lf[0], lf[1]); L.y = pack_bf16x2(lf[2], lf[3]);
        hi[i + u * q] = H;
        lo[i + u * q] = L;
    }
}

// ---------------------------------------------------------------------------
// GEMM: C[M,N] = A[M,K] * B[N,K]^T  (bf16 hi/lo x3 MMAs, fp32 out)
// Tile 128x64x32, 128 threads = 4 warps, 3-stage ring, 3 CTAs/SM. (R11 proven)
// ---------------------------------------------------------------------------
#define TBM 128
#define TBN 64
#define TBK 32
#define OFF_AH 0
#define OFF_AL 8192
#define OFF_BH 16384
#define OFF_BL 20480
#define STAGE_BYTES 24576
#define GEMM_SMEM (3 * STAGE_BYTES)   // 72 KB

__device__ __forceinline__ uint32_t mrow_off(int r, int kc) {
    const int mr = r >> 1;
    const int ch = (((r & 1) << 2) | kc) ^ (mr & 7);
    return (uint32_t)(mr * 128 + ch * 16);
}

__global__ __launch_bounds__(128, 3) void gemm_mma_kernel(
    const __nv_bfloat16* __restrict__ Ah, const __nv_bfloat16* __restrict__ Al,
    const __nv_bfloat16* __restrict__ Bh, const __nv_bfloat16* __restrict__ Bl,
    float* __restrict__ C0, float* __restrict__ C1,
    __nv_bfloat16* __restrict__ C2h, __nv_bfloat16* __restrict__ C2l,
    int ns1, int ns2, int ldc0, int ldc1, int ldc2,
    int M, int N, int K)
{
    extern __shared__ __align__(1024) char smem[];
    const uint32_t sbase = smem_u32(smem);
    const int tid  = threadIdx.x;
    const int lane = tid & 31;
    const int wid  = tid >> 5;
    const int wm   = wid & 1;
    const int wn   = wid >> 1;
    const int m0   = blockIdx.y * TBM;
    const int n0   = blockIdx.x * TBN;
    const int r0c = tid >> 2, c0c = tid & 3;

    float acc[4][4][4];
#pragma unroll
    for (int i = 0; i < 4; i++)
#pragma unroll
        for (int j = 0; j < 4; j++)
#pragma unroll
            for (int t = 0; t < 4; t++) acc[i][j][t] = 0.0f;

    const int nch = K / TBK;

    auto issue = [&](int s, int k0) {
        const uint32_t st = sbase + s * STAGE_BYTES;
#pragma unroll
        for (int i = 0; i < 4; i++) {
            const int r = r0c + i * 32;
            const uint32_t off = mrow_off(r, c0c);
            const size_t ga = (size_t)(m0 + r) * K + k0 + c0c * 8;
            cp16(st + OFF_AH + off, Ah + ga);
            cp16(st + OFF_AL + off, Al + ga);
        }
#pragma unroll
        for (int i = 0; i < 2; i++) {
            const int r = r0c + i * 32;
            const uint32_t off = mrow_off(r, c0c);
            const size_t gb = (size_t)(n0 + r) * K + k0 + c0c * 8;
            cp16(st + OFF_BH + off, Bh + gb);
            cp16(st + OFF_BL + off, Bl + gb);
        }
        cp_commit();
    };

    issue(0, 0);
    issue(1, TBK);

    for (int ch = 0; ch < nch; ch++) {
        if (ch < nch - 1) cp_wait<1>();
        else              cp_wait<0>();
        __syncthreads();

        const int s = ch % 3;
        const uint32_t stAh = sbase + s * STAGE_BYTES + OFF_AH;
        const uint32_t stAl = sbase + s * STAGE_BYTES + OFF_AL;
        const uint32_t stBh = sbase + s * STAGE_BYTES + OFF_BH;
        const uint32_t stBl = sbase + s * STAGE_BYTES + OFF_BL;
#pragma unroll
        for (int kt = 0; kt < 2; kt++) {
            uint32_t ah[4][4], al[4][4], bh[2][4], bl[2][4];
#pragma unroll
            for (int mt = 0; mt < 4; mt++) {
                ldm_x4_k32(ah[mt], stAh, wm * 64 + mt * 16, kt);
                ldm_x4_k32(al[mt], stAl, wm * 64 + mt * 16, kt);
            }
#pragma unroll
            for (int bp = 0; bp < 2; bp++) {
                ldm_x4_k32(bh[bp], stBh, wn * 32 + bp * 16, kt);
                ldm_x4_k32(bl[bp], stBl, wn * 32 + bp * 16, kt);
            }
#pragma unroll
            for (int mt = 0; mt < 4; mt++)
#pragma unroll
                for (int nt = 0; nt < 4; nt++) {
                    const int bp = nt >> 1, o = nt & 1;
                    mma_bf16(acc[mt][nt], ah[mt], bh[bp][o], bh[bp][o + 2]);
                    mma_bf16(acc[mt][nt], ah[mt], bl[bp][o], bl[bp][o + 2]);
                    mma_bf16(acc[mt][nt], al[mt], bh[bp][o], bh[bp][o + 2]);
                }
        }

        if (ch + 2 < nch) issue((ch + 2) % 3, (ch + 2) * TBK);
    }

    if (n0 >= ns2 && C2h != nullptr) {
        const int nc0 = n0 - ns2;
#pragma unroll
        for (int mt = 0; mt < 4; mt++) {
            const int row = m0 + wm * 64 + mt * 16 + (lane >> 2);
#pragma unroll
            for (int nt = 0; nt < 4; nt++) {
                const int col = nc0 + wn * 32 + nt * 8 + (lane & 3) * 2;
                uint32_t h0, l0v, h1, l1v;
                pack_hilo(acc[mt][nt][0], acc[mt][nt][1], h0, l0v);
                pack_hilo(acc[mt][nt][2], acc[mt][nt][3], h1, l1v);
                *(uint32_t*)(C2h + (size_t)row * ldc2 + col)       = h0;
                *(uint32_t*)(C2l + (size_t)row * ldc2 + col)       = l0v;
                *(uint32_t*)(C2h + (size_t)(row + 8) * ldc2 + col) = h1;
                *(uint32_t*)(C2l + (size_t)(row + 8) * ldc2 + col) = l1v;
            }
        }
        return;
    }
    float* Cb; int ldc, nc0;
    if (n0 < ns1) { Cb = C0; ldc = ldc0; nc0 = n0; }
    else          { Cb = C1; ldc = ldc1; nc0 = n0 - ns1; }
#pragma unroll
    for (int mt = 0; mt < 4; mt++) {
        const int row = m0 + wm * 64 + mt * 16 + (lane >> 2);
#pragma unroll
        for (int nt = 0; nt < 4; nt++) {
            const int col = nc0 + wn * 32 + nt * 8 + (lane & 3) * 2;
            float2 v0 = make_float2(acc[mt][nt][0], acc[mt][nt][1]);
            float2 v1 = make_float2(acc[mt][nt][2], acc[mt][nt][3]);
            *(float2*)(Cb + (size_t)row * ldc + col)       = v0;
            *(float2*)(Cb + (size_t)(row + 8) * ldc + col) = v1;
        }
    }
}

// ---------------------------------------------------------------------------
// RoPE + fp32 -> bf16 hi/lo for q, k (vectorized float2 / bf16x2)
// ---------------------------------------------------------------------------
__global__ __launch_bounds__(256) void rope_cvt_kernel(
    const float* __restrict__ q, const float* __restrict__ k,
    const int* __restrict__ pos,
    __nv_bfloat16* __restrict__ qh, __nv_bfloat16* __restrict__ ql,
    __nv_bfloat16* __restrict__ kh, __nv_bfloat16* __restrict__ kl)
{
    const int bs = blockIdx.x;
    const float p = (float)pos[bs];
    const float c1 = -0.2076205059304601f;        // -log2(10000)/64
    for (int i = threadIdx.x; i < 1280; i += 256) {
        const float* base; size_t idx; int dp;
        __nv_bfloat16 *H, *L;
        if (i < 1024) {
            int hh = i >> 5; dp = (i & 31) * 2;
            idx = ((size_t)bs * NH + hh) * HD;
            base = q + idx; H = qh; L = ql;
        } else {
            int j = i - 1024;
            int hh = j >> 5; dp = (j & 31) * 2;
            idx = ((size_t)bs * NKV + hh) * HD;
            base = k + idx; H = kh; L = kl;
        }
        float2 x1 = *(const float2*)(base + dp);
        float2 x2 = *(const float2*)(base + dp + 64);
        float o1[2], o2[2];
#pragma unroll
        for (int t = 0; t < 2; t++) {
            float inv = exp2f(c1 * (float)(dp + t));
            float ang = p * inv;
            float sv, cv;
            sincosf(ang, &sv, &cv);
            float a  = t ? x1.y : x1.x;
            float b2 = t ? x2.y : x2.x;
            o1[t] = a * cv - b2 * sv;
            o2[t] = b2 * cv + a * sv;
        }
        uint32_t hA, lA, hB, lB;
        pack_hilo(o1[0], o1[1], hA, lA);
        pack_hilo(o2[0], o2[1], hB, lB);
        *(uint32_t*)(H + idx + dp)      = hA;
        *(uint32_t*)(L + idx + dp)      = lA;
        *(uint32_t*)(H + idx + dp + 64) = hB;
        *(uint32_t*)(L + idx + dp + 64) = lB;
    }
}

// ---------------------------------------------------------------------------
// Flash attention via mma.sync (bf16 hi/lo x3), fp32 softmax (exp2), causal.
// CTA: 64 q-rows x 1 head, 4 warps, 64KB smem + <=170 regs -> 3 CTAs/SM.
// Q resident in smem (no fragment hoist); 2-stage ABKV=16 KV ring.
// ---------------------------------------------------------------------------
#define ABQ  64
#define ABKV 16
#define AQH 0
#define AQL 16384
#define KV0 32768          // per-stage: KH 0, KL 4K, VH 8K, VL 12K
#define SKH 0
#define SKL 4096
#define SVH 8192
#define SVL 12288
#define KVSTAGE 16384
#define ATTN_SMEM (32768 + 2 * KVSTAGE)   // 64 KB

__global__ __launch_bounds__(128, 3) void attn_mma_kernel(
    const __nv_bfloat16* __restrict__ Qh, const __nv_bfloat16* __restrict__ Ql,
    const __nv_bfloat16* __restrict__ Kh, const __nv_bfloat16* __restrict__ Kl,
    const __nv_bfloat16* __restrict__ Vh, const __nv_bfloat16* __restrict__ Vl,
    __nv_bfloat16* __restrict__ AOh, __nv_bfloat16* __restrict__ AOl)
{
    extern __shared__ __align__(1024) char smem[];
    const uint32_t sbase = smem_u32(smem);
    const int tid  = threadIdx.x;
    const int lane = tid & 31;
    const int wq   = tid >> 5;                              // 0..3
    const int qb   = (int)gridDim.x - 1 - (int)blockIdx.x;  // big tiles first
    const int h    = blockIdx.y, b = blockIdx.z;
    const int g    = h / NREP;
    const int q0   = qb * ABQ;
    const int rowmin = q0 + wq * 16;
    const int lr8 = tid >> 4;      // 0..7 row within 8-row pass
    const int lc  = tid & 15;      // 16B chunk within 256B row

    // ---- Q tile (resident) + first KV tile: one cp.async group ----
#pragma unroll
    for (int i = 0; i < 8; i++) {
        const int row = i * 8 + lr8;
        const uint32_t off = (uint32_t)(row * 256 + ((lc ^ (row & 7)) * 16));
        const size_t gp = ((size_t)(b * S_LEN + q0 + row) * NH + h) * HD + lc * 8;
        cp16(sbase + AQH + off, Qh + gp);
        cp16(sbase + AQL + off, Ql + gp);
    }
    auto issue_kv = [&](int s, int k0, bool commit) {
        const uint32_t st = sbase + KV0 + s * KVSTAGE;
#pragma unroll
        for (int i = 0; i < 2; i++) {
            const int row = i * 8 + lr8;
            const uint32_t off = (uint32_t)(row * 256 + ((lc ^ (row & 7)) * 16));
            const size_t gp = ((size_t)(b * S_LEN + k0 + row) * NKV + g) * HD + lc * 8;
            cp16(st + SKH + off, Kh + gp);
            cp16(st + SKL + off, Kl + gp);
            cp16(st + SVH + off, Vh + gp);
            cp16(st + SVL + off, Vl + gp);
        }
        if (commit) cp_commit();
    };
    issue_kv(0, 0, false);
    cp_commit();                      // group0 = Q + KV0
    const int ntile = 4 * qb + 4;

    float out[16][4];
#pragma unroll
    for (int i = 0; i < 16; i++)
#pragma unroll
        for (int j = 0; j < 4; j++) out[i][j] = 0.0f;
    float m0 = -1e30f, m1 = -1e30f, l0 = 0.0f, l1 = 0.0f;
    const float scl2 = 0.08838834764831845f * 1.4426950408889634f;  // /sqrt(128)*log2(e)

    for (int kb = 0; kb < ntile; kb++) {
        const int s = kb & 1;
        const int k0 = kb * ABKV;
        if (kb + 1 < ntile) {
            issue_kv(1 - s, (kb + 1) * ABKV, true);
            cp_wait<1>();
        } else {
            cp_wait<0>();
        }
        __syncthreads();

        if (k0 <= rowmin + 15) {   // else tile fully masked for this warp
            const uint32_t stK = sbase + KV0 + s * KVSTAGE;

            // ---- S = Q K^T  (16 x 16 x 128) ----
            float sc[2][4];
#pragma unroll
            for (int nt = 0; nt < 2; nt++)
#pragma unroll
                for (int j = 0; j < 4; j++) sc[nt][j] = 0.0f;
#pragma unroll
            for (int kt = 0; kt < 8; kt++) {
                uint32_t aqh[4], aql[4], bkh[4], bkl[4];
                ldm_x4_256(aqh, sbase + AQH, wq * 16, kt * 2);
                ldm_x4_256(aql, sbase + AQL, wq * 16, kt * 2);
                ldm_x4_256(bkh, stK + SKH, 0, kt * 2);
                ldm_x4_256(bkl, stK + SKL, 0, kt * 2);
#pragma unroll
                for (int o = 0; o < 2; o++) {
                    mma_bf16(sc[o], aqh, bkh[o], bkh[o + 2]);
                    mma_bf16(sc[o], aqh, bkl[o], bkl[o + 2]);
                    mma_bf16(sc[o], aql, bkh[o], bkh[o + 2]);
                }
            }

            // ---- scale + causal mask + online softmax (exp2 domain) ----
            const int r0g = rowmin + (lane >> 2);
            const bool domask = (k0 + ABKV - 1) > rowmin;
            float mx0 = -1e30f, mx1 = -1e30f;
#pragma unroll
            for (int nt = 0; nt < 2; nt++) {
#pragma unroll
                for (int j = 0; j < 4; j++) {
                    float v = sc[nt][j] * scl2;
                    if (domask) {
                        int cg = k0 + nt * 8 + (lane & 3) * 2 + (j & 1);
                        int rg = r0g + ((j >> 1) << 3);
                        if (cg > rg) v = -1e30f;
                    }
                    sc[nt][j] = v;
                }
                mx0 = fmaxf(mx0, fmaxf(sc[nt][0], sc[nt][1]));
                mx1 = fmaxf(mx1, fmaxf(sc[nt][2], sc[nt][3]));
            }
            mx0 = fmaxf(mx0, __shfl_xor_sync(0xffffffffu, mx0, 1));
            mx0 = fmaxf(mx0, __shfl_xor_sync(0xffffffffu, mx0, 2));
            mx1 = fmaxf(mx1, __shfl_xor_sync(0xffffffffu, mx1, 1));
            mx1 = fmaxf(mx1, __shfl_xor_sync(0xffffffffu, mx1, 2));
            const float mn0 = fmaxf(m0, mx0), mn1 = fmaxf(m1, mx1);
            const float a0 = exp2f(m0 - mn0), a1 = exp2f(m1 - mn1);
            m0 = mn0; m1 = mn1;
            float ps0 = 0.0f, ps1 = 0.0f;
#pragma unroll
            for (int nt = 0; nt < 2; nt++) {
                sc[nt][0] = exp2f(sc[nt][0] - mn0); ps0 += sc[nt][0];
                sc[nt][1] = exp2f(sc[nt][1] - mn0); ps0 += sc[nt][1];
                sc[nt][2] = exp2f(sc[nt][2] - mn1); ps1 += sc[nt][2];
                sc[nt][3] = exp2f(sc[nt][3] - mn1); ps1 += sc[nt][3];
            }
            l0 = l0 * a0 + ps0;
            l1 = l1 * a1 + ps1;
#pragma unroll
            for (int dt = 0; dt < 16; dt++) {
                out[dt][0] *= a0; out[dt][1] *= a0;
                out[dt][2] *= a1; out[dt][3] *= a1;
            }

            // ---- O += P V  (16 x 128 x 16) ----
            uint32_t aph[4], apl[4];
            pack_hilo(sc[0][0], sc[0][1], aph[0], apl[0]);
            pack_hilo(sc[0][2], sc[0][3], aph[1], apl[1]);
            pack_hilo(sc[1][0], sc[1][1], aph[2], apl[2]);
            pack_hilo(sc[1][2], sc[1][3], aph[3], apl[3]);
#pragma unroll
            for (int dt = 0; dt < 8; dt++) {
                uint32_t bvh[4], bvl[4];
                ldm_x4t_256(bvh, stK + SVH, 0, dt * 2);
                ldm_x4t_256(bvl, stK + SVL, 0, dt * 2);
                mma_bf16(out[dt * 2],     aph, bvh[0], bvh[1]);
                mma_bf16(out[dt * 2],     aph, bvl[0], bvl[1]);
                mma_bf16(out[dt * 2],     apl, bvh[0], bvh[1]);
                mma_bf16(out[dt * 2 + 1], aph, bvh[2], bvh[3]);
                mma_bf16(out[dt * 2 + 1], aph, bvl[2], bvl[3]);
                mma_bf16(out[dt * 2 + 1], apl, bvh[2], bvh[3]);
            }
        }
        __syncthreads();   // all warps done with slot s before it is refilled
    }

    // ---- finalize: write bf16 hi/lo directly (feeds O-projection GEMM) ----
    l0 += __shfl_xor_sync(0xffffffffu, l0, 1);
    l0 += __shfl_xor_sync(0xffffffffu, l0, 2);
    l1 += __shfl_xor_sync(0xffffffffu, l1, 1);
    l1 += __shfl_xor_sync(0xffffffffu, l1, 2);
    const float i0 = 1.0f / l0, i1 = 1.0f / l1;
    const int r0g = rowmin + (lane >> 2);
    const size_t base0 = ((size_t)(b * S_LEN + r0g) * NH + h) * HD;
    const size_t base1 = base0 + (size_t)8 * NH * HD;
#pragma unroll
    for (int dt = 0; dt < 16; dt++) {
        const int col = dt * 8 + (lane & 3) * 2;
        uint32_t h0, l0p, h1, l1p;
        pack_hilo(out[dt][0] * i0, out[dt][1] * i0, h0, l0p);
        pack_hilo(out[dt][2] * i1, out[dt][3] * i1, h1, l1p);
        *(uint32_t*)(AOh + base0 + col) = h0;
        *(uint32_t*)(AOl + base0 + col) = l0p;
        *(uint32_t*)(AOh + base1 + col) = h1;
        *(uint32_t*)(AOl + base1 + col) = l1p;
    }
}

// ---------------------------------------------------------------------------
// Launch
// ---------------------------------------------------------------------------
extern "C" void kernel_launch(void* const* d_in, const int* in_sizes, int n_in,
                              void* d_out, int out_size)
{
    const float* hs = (const float*)d_in[0];
    const float* wq = (const float*)d_in[1];
    const float* wk = (const float*)d_in[2];
    const float* wv = (const float*)d_in[3];
    const float* wo = (const float*)d_in[4];
    const int*  pos = (const int*)  d_in[6];
    float*      out = (float*)d_out;

    float *q, *k;
    cudaGetSymbolAddress((void**)&q,  g_q);
    cudaGetSymbolAddress((void**)&k,  g_k);

    __nv_bfloat16 *hsh, *hsl, *wh, *wl, *woh, *wol, *aoh, *aol;
    __nv_bfloat16 *qh, *ql, *kh, *kl, *vh, *vl;
    cudaGetSymbolAddress((void**)&hsh, g_hs_h); cudaGetSymbolAddress((void**)&hsl, g_hs_l);
    cudaGetSymbolAddress((void**)&wh,  g_w_h);  cudaGetSymbolAddress((void**)&wl,  g_w_l);
    cudaGetSymbolAddress((void**)&woh, g_wo_h); cudaGetSymbolAddress((void**)&wol, g_wo_l);
    cudaGetSymbolAddress((void**)&aoh, g_ao_h); cudaGetSymbolAddress((void**)&aol, g_ao_l);
    cudaGetSymbolAddress((void**)&qh,  g_q_h);  cudaGetSymbolAddress((void**)&ql,  g_q_l);
    cudaGetSymbolAddress((void**)&kh,  g_k_h);  cudaGetSymbolAddress((void**)&kl,  g_k_l);
    cudaGetSymbolAddress((void**)&vh,  g_v_h);  cudaGetSymbolAddress((void**)&vl,  g_v_l);

    cudaFuncSetAttribute(gemm_mma_kernel, cudaFuncAttributeMaxDynamicSharedMemorySize, GEMM_SMEM);
    cudaFuncSetAttribute(attn_mma_kernel, cudaFuncAttributeMaxDynamicSharedMemorySize, ATTN_SMEM);

    // One merged conversion launch for all five inputs (MLP=8 per thread).
    cvt_all_kernel<<<CVT_BLOCKS, 256>>>(
        (const float4*)hs, (uint2*)hsh, (uint2*)hsl,
        (const float4*)wq, (uint2*)wh,              (uint2*)wl,
        (const float4*)wk, (uint2*)(wh + 16777216u), (uint2*)(wl + 16777216u),
        (const float4*)wv, (uint2*)(wh + 20971520u), (uint2*)(wl + 20971520u),
        (const float4*)wo, (uint2*)woh, (uint2*)wol);

    // Merged QKV projection: N = 6144; q,k -> fp32, v -> bf16 hi/lo directly
    gemm_mma_kernel<<<dim3(6144 / TBN, MROWS / TBM), 128, GEMM_SMEM>>>(
        hsh, hsl, wh, wl, q, k, vh, vl,
        4096, 5120, NH * HD, NKV * HD, NKV * HD,
        MROWS, 6144, HID);

    // RoPE + hi/lo conversion for q, k
    rope_cvt_kernel<<<MROWS, 256>>>(q, k, pos, qh, ql, kh, kl);

    // Causal flash attention (mma.sync, 3 CTAs/SM, 2-stage ABKV=16 ring)
    attn_mma_kernel<<<dim3(S_LEN / ABQ, NH, B_SZ), 128, ATTN_SMEM>>>(
        qh, ql, kh, kl, vh, vl, aoh, aol);

    // Output projection
    gemm_mma_kernel<<<dim3(HID / TBN, MROWS / TBM), 128, GEMM_SMEM>>>(
        aoh, aol, woh, wol, out, out, nullptr, nullptr,
        HID, HID, HID, HID, HID,
        MROWS, HID, NH * HD);
}

// round 14
// speedup vs baseline: 1.0123x; 1.0123x over previous
#include <cuda_runtime.h>
#include <cuda_bf16.h>
#include <cstdint>

// Problem constants (fixed shapes)
#define NH    32
#define NKV   8
#define HD    128
#define S_LEN 2048
#define B_SZ  2
#define HID   4096
#define MROWS (B_SZ * S_LEN)   // 4096
#define NREP  (NH / NKV)       // 4

#define E16M (16u * 1024u * 1024u)
#define E4M  (4u  * 1024u * 1024u)
#define WQKV_E (6144u * 4096u)   // combined q|k|v weight rows

// ---------------------------------------------------------------------------
// Scratch (device globals; allocation-free per harness rules)
// ---------------------------------------------------------------------------
// bf16 hi/lo copies
__device__ __nv_bfloat16 g_hs_h[E16M],  g_hs_l[E16M];
__device__ __nv_bfloat16 g_w_h[WQKV_E], g_w_l[WQKV_E];   // wq|wk|wv combined
__device__ __nv_bfloat16 g_wo_h[E16M],  g_wo_l[E16M];
__device__ __nv_bfloat16 g_ao_h[E16M],  g_ao_l[E16M];
// post-rope bf16 hi/lo q/k, direct-split v for attention
__device__ __nv_bfloat16 g_q_h[E16M], g_q_l[E16M];
__device__ __nv_bfloat16 g_k_h[E4M],  g_k_l[E4M];
__device__ __nv_bfloat16 g_v_h[E4M],  g_v_l[E4M];

// ---------------------------------------------------------------------------
// Common helpers (sm_80-level PTX only; no 'a'-suffix features)
// ---------------------------------------------------------------------------
__device__ __forceinline__ uint32_t smem_u32(const void* p) {
    uint32_t a;
    asm("{ .reg .u64 t; cvta.to.shared.u64 t, %1; cvt.u32.u64 %0, t; }"
        : "=r"(a) : "l"(p));
    return a;
}
__device__ __forceinline__ uint32_t pack_bf16x2(float a, float b) {
    __nv_bfloat162 h = __floats2bfloat162_rn(a, b);
    return *reinterpret_cast<uint32_t*>(&h);
}
__device__ __forceinline__ void cp16(uint32_t saddr, const void* gptr) {
    asm volatile("cp.async.cg.shared.global [%0], [%1], 16;"
                 :: "r"(saddr), "l"(gptr));
}
__device__ __forceinline__ void cp_commit() {
    asm volatile("cp.async.commit_group;" ::: "memory");
}
template <int N>
__device__ __forceinline__ void cp_wait() {
    asm volatile("cp.async.wait_group %0;" :: "n"(N) : "memory");
}
// ldmatrix.x4 over macro-row layout: logical rows of 32 bf16 (64B) packed in
// pairs into 128B macro-rows with the standard XOR-8 swizzle.
__device__ __forceinline__ void ldm_x4_k32(uint32_t* r, uint32_t base, int row0, int kt) {
    const int l  = (int)(threadIdx.x & 31);
    const int rr = row0 + (l & 15);
    const int kc = 2 * kt + (l >> 4);
    const int mr = rr >> 1;
    const int ch = (((rr & 1) << 2) | kc) ^ (mr & 7);
    const uint32_t addr = base + (uint32_t)(mr * 128 + ch * 16);
    asm volatile("ldmatrix.sync.aligned.m8n8.x4.shared.b16 {%0,%1,%2,%3}, [%4];"
                 : "=r"(r[0]), "=r"(r[1]), "=r"(r[2]), "=r"(r[3]) : "r"(addr));
}
// ldmatrix.x4, 256B-wide rows (attention tiles, HD=128 bf16 per row)
__device__ __forceinline__ void ldm_x4_256(uint32_t* r, uint32_t base, int row0, int c0) {
    const int l  = (int)(threadIdx.x & 31);
    const int rr = row0 + (l & 15);
    const int cc = (c0 + (l >> 4)) ^ (rr & 7);
    const uint32_t addr = base + (uint32_t)(rr * 256 + cc * 16);
    asm volatile("ldmatrix.sync.aligned.m8n8.x4.shared.b16 {%0,%1,%2,%3}, [%4];"
                 : "=r"(r[0]), "=r"(r[1]), "=r"(r[2]), "=r"(r[3]) : "r"(addr));
}
__device__ __forceinline__ void ldm_x4t_256(uint32_t* r, uint32_t base, int row0, int c0) {
    const int l  = (int)(threadIdx.x & 31);
    const int rr = row0 + (l & 15);
    const int cc = (c0 + (l >> 4)) ^ (rr & 7);
    const uint32_t addr = base + (uint32_t)(rr * 256 + cc * 16);
    asm volatile("ldmatrix.sync.aligned.m8n8.x4.trans.shared.b16 {%0,%1,%2,%3}, [%4];"
                 : "=r"(r[0]), "=r"(r[1]), "=r"(r[2]), "=r"(r[3]) : "r"(addr));
}
__device__ __forceinline__ void mma_bf16(float* d, const uint32_t* a,
                                         uint32_t b0, uint32_t b1) {
    asm volatile(
        "mma.sync.aligned.m16n8k16.row.col.f32.bf16.bf16.f32 "
        "{%0,%1,%2,%3}, {%4,%5,%6,%7}, {%8,%9}, {%0,%1,%2,%3};"
        : "+f"(d[0]), "+f"(d[1]), "+f"(d[2]), "+f"(d[3])
        : "r"(a[0]), "r"(a[1]), "r"(a[2]), "r"(a[3]), "r"(b0), "r"(b1));
}
__device__ __forceinline__ void pack_hilo(float p0, float p1, uint32_t& hi, uint32_t& lo) {
    float h0 = __bfloat162float(__float2bfloat16(p0));
    float h1 = __bfloat162float(__float2bfloat16(p1));
    hi = pack_bf16x2(h0, h1);
    lo = pack_bf16x2(p0 - h0, p1 - h1);
}
__device__ __forceinline__ void store_hilo(__nv_bfloat16* H, __nv_bfloat16* L,
                                           size_t idx, float val) {
    __nv_bfloat16 hb = __float2bfloat16(val);
    H[idx] = hb;
    L[idx] = __float2bfloat16(val - __bfloat162float(hb));
}

// ---------------------------------------------------------------------------
// Merged fp32 -> bf16 hi/lo conversion for all 5 inputs, one launch, MLP=8.
// wq/wk rows are PERMUTED on write: within each head, column order becomes
// (d0, d0+64, d1, d1+65, ...) so the GEMM epilogue holds RoPE pairs locally.
// ---------------------------------------------------------------------------
#define CVT_BLOCKS 7168

__global__ __launch_bounds__(256) void cvt_all_kernel(
    const float4* __restrict__ s0, uint2* __restrict__ h0, uint2* __restrict__ l0,
    const float4* __restrict__ s1, uint2* __restrict__ h1, uint2* __restrict__ l1,
    const float4* __restrict__ s2, uint2* __restrict__ h2, uint2* __restrict__ l2,
    const float4* __restrict__ s3, uint2* __restrict__ h3, uint2* __restrict__ l3,
    const float4* __restrict__ s4, uint2* __restrict__ h4, uint2* __restrict__ l4)
{
    const int blk = blockIdx.x;
    const float4* x; uint2* hi; uint2* lo; int base; int q; bool perm;
    if (blk < 2048)      { x = s0; hi = h0; lo = l0; base = blk;        q = 524288; perm = false; }
    else if (blk < 4096) { x = s1; hi = h1; lo = l1; base = blk - 2048; q = 524288; perm = true;  }
    else if (blk < 4608) { x = s2; hi = h2; lo = l2; base = blk - 4096; q = 131072; perm = true;  }
    else if (blk < 5120) { x = s3; hi = h3; lo = l3; base = blk - 4608; q = 131072; perm = false; }
    else                 { x = s4; hi = h4; lo = l4; base = blk - 5120; q = 524288; perm = false; }

    const int i = base * 256 + (int)threadIdx.x;
    float4 f[8];
#pragma unroll
    for (int u = 0; u < 8; u++) f[u] = x[i + u * q];   // 8 independent LDGs
#pragma unroll
    for (int u = 0; u < 8; u++) {
        float xs[4] = {f[u].x, f[u].y, f[u].z, f[u].w};
        float hf[4], lf[4];
#pragma unroll
        for (int t = 0; t < 4; t++) {
            __nv_bfloat16 h = __float2bfloat16(xs[t]);
            hf[t] = __bfloat162float(h);
            lf[t] = xs[t] - hf[t];
        }
        uint2 H, L;
        H.x = pack_bf16x2(hf[0], hf[1]); H.y = pack_bf16x2(hf[2], hf[3]);
        L.x = pack_bf16x2(lf[0], lf[1]); L.y = pack_bf16x2(lf[2], lf[3]);
        int j = i + u * q;
        if (perm) {
            // row e = weight row (4096 elems = 1024 uint2 per row)
            const int e = j >> 10, off = j & 1023;
            const int hrow = e >> 7, d = e & 127;
            const int dp = (d < 64) ? (2 * d) : (2 * (d - 64) + 1);
            j = ((hrow << 7) | dp) * 1024 + off;
        }
        hi[j] = H;
        lo[j] = L;
    }
}

// ---------------------------------------------------------------------------
// GEMM: C[M,N] = A[M,K] * B[N,K]^T  (bf16 hi/lo x3 MMAs)
// Tile 128x64x32, 128 threads = 4 warps, 3-stage ring, 3 CTAs/SM.
// Epilogues: RoPE->bf16 hi/lo (q/k, interleaved-weight layout), bf16 hi/lo (v),
// or fp32 (o-projection).
// ---------------------------------------------------------------------------
#define TBM 128
#define TBN 64
#define TBK 32
#define OFF_AH 0
#define OFF_AL 8192
#define OFF_BH 16384
#define OFF_BL 20480
#define STAGE_BYTES 24576
#define GEMM_SMEM (3 * STAGE_BYTES)   // 72 KB

__device__ __forceinline__ uint32_t mrow_off(int r, int kc) {
    const int mr = r >> 1;
    const int ch = (((r & 1) << 2) | kc) ^ (mr & 7);
    return (uint32_t)(mr * 128 + ch * 16);
}

__global__ __launch_bounds__(128, 3) void gemm_mma_kernel(
    const __nv_bfloat16* __restrict__ Ah, const __nv_bfloat16* __restrict__ Al,
    const __nv_bfloat16* __restrict__ Bh, const __nv_bfloat16* __restrict__ Bl,
    const int* __restrict__ pos,                        // non-null: rope epilogue for n0<ns2
    __nv_bfloat16* __restrict__ Qh, __nv_bfloat16* __restrict__ Ql,
    __nv_bfloat16* __restrict__ Kh, __nv_bfloat16* __restrict__ Kl,
    float* __restrict__ C0,
    __nv_bfloat16* __restrict__ C2h, __nv_bfloat16* __restrict__ C2l,
    int ns1, int ns2, int ldc0, int ldc2,
    int M, int N, int K)
{
    extern __shared__ __align__(1024) char smem[];
    const uint32_t sbase = smem_u32(smem);
    const int tid  = threadIdx.x;
    const int lane = tid & 31;
    const int wid  = tid >> 5;
    const int wm   = wid & 1;
    const int wn   = wid >> 1;
    const int m0   = blockIdx.y * TBM;
    const int n0   = blockIdx.x * TBN;
    const int r0c = tid >> 2, c0c = tid & 3;

    float acc[4][4][4];
#pragma unroll
    for (int i = 0; i < 4; i++)
#pragma unroll
        for (int j = 0; j < 4; j++)
#pragma unroll
            for (int t = 0; t < 4; t++) acc[i][j][t] = 0.0f;

    const int nch = K / TBK;

    auto issue = [&](int s, int k0) {
        const uint32_t st = sbase + s * STAGE_BYTES;
#pragma unroll
        for (int i = 0; i < 4; i++) {
            const int r = r0c + i * 32;
            const uint32_t off = mrow_off(r, c0c);
            const size_t ga = (size_t)(m0 + r) * K + k0 + c0c * 8;
            cp16(st + OFF_AH + off, Ah + ga);
            cp16(st + OFF_AL + off, Al + ga);
        }
#pragma unroll
        for (int i = 0; i < 2; i++) {
            const int r = r0c + i * 32;
            const uint32_t off = mrow_off(r, c0c);
            const size_t gb = (size_t)(n0 + r) * K + k0 + c0c * 8;
            cp16(st + OFF_BH + off, Bh + gb);
            cp16(st + OFF_BL + off, Bl + gb);
        }
        cp_commit();
    };

    issue(0, 0);
    issue(1, TBK);

    for (int ch = 0; ch < nch; ch++) {
        if (ch < nch - 1) cp_wait<1>();
        else              cp_wait<0>();
        __syncthreads();

        const int s = ch % 3;
        const uint32_t stAh = sbase + s * STAGE_BYTES + OFF_AH;
        const uint32_t stAl = sbase + s * STAGE_BYTES + OFF_AL;
        const uint32_t stBh = sbase + s * STAGE_BYTES + OFF_BH;
        const uint32_t stBl = sbase + s * STAGE_BYTES + OFF_BL;
#pragma unroll
        for (int kt = 0; kt < 2; kt++) {
            uint32_t ah[4][4], al[4][4], bh[2][4], bl[2][4];
#pragma unroll
            for (int mt = 0; mt < 4; mt++) {
                ldm_x4_k32(ah[mt], stAh, wm * 64 + mt * 16, kt);
                ldm_x4_k32(al[mt], stAl, wm * 64 + mt * 16, kt);
            }
#pragma unroll
            for (int bp = 0; bp < 2; bp++) {
                ldm_x4_k32(bh[bp], stBh, wn * 32 + bp * 16, kt);
                ldm_x4_k32(bl[bp], stBl, wn * 32 + bp * 16, kt);
            }
#pragma unroll
            for (int mt = 0; mt < 4; mt++)
#pragma unroll
                for (int nt = 0; nt < 4; nt++) {
                    const int bp = nt >> 1, o = nt & 1;
                    mma_bf16(acc[mt][nt], ah[mt], bh[bp][o], bh[bp][o + 2]);
                    mma_bf16(acc[mt][nt], ah[mt], bl[bp][o], bl[bp][o + 2]);
                    mma_bf16(acc[mt][nt], al[mt], bh[bp][o], bh[bp][o + 2]);
                }
        }

        if (ch + 2 < nch) issue((ch + 2) % 3, (ch + 2) * TBK);
    }

    // ---- epilogues ----
    if (pos != nullptr && n0 < ns2) {
        // RoPE path: interleaved weight layout -> acc pairs are (x_d, x_{d+64})
        const float c1 = -0.2076205059304601f;   // -log2(10000)/64
        const int sec = (n0 < ns1) ? 0 : 1;
        const int nq  = sec ? (n0 - ns1) : n0;
        const int head = nq >> 7;
        __nv_bfloat16 *H = sec ? Kh : Qh;
        __nv_bfloat16 *L = sec ? Kl : Ql;
        const int hdstr = sec ? (NKV * HD) : (NH * HD);
        const int dbase = ((nq & 127) >> 1) + wn * 16 + (lane & 3);
        float inv[4];
#pragma unroll
        for (int nt = 0; nt < 4; nt++)
            inv[nt] = exp2f(c1 * (float)(dbase + nt * 4));
#pragma unroll
        for (int mt = 0; mt < 4; mt++) {
            const int row0 = m0 + wm * 64 + mt * 16 + (lane >> 2);
#pragma unroll
            for (int rr = 0; rr < 2; rr++) {
                const int r = row0 + rr * 8;
                const float p = (float)pos[r];
                const size_t bidx = (size_t)r * hdstr + head * 128;
#pragma unroll
                for (int nt = 0; nt < 4; nt++) {
                    float sv, cv;
                    sincosf(p * inv[nt], &sv, &cv);
                    const float xd = acc[mt][nt][rr * 2 + 0];
                    const float xD = acc[mt][nt][rr * 2 + 1];
                    const int d = dbase + nt * 4;
                    store_hilo(H, L, bidx + d,      xd * cv - xD * sv);
                    store_hilo(H, L, bidx + d + 64, xD * cv + xd * sv);
                }
            }
        }
        return;
    }
    if (n0 >= ns2 && C2h != nullptr) {
        const int nc0 = n0 - ns2;
#pragma unroll
        for (int mt = 0; mt < 4; mt++) {
            const int row = m0 + wm * 64 + mt * 16 + (lane >> 2);
#pragma unroll
            for (int nt = 0; nt < 4; nt++) {
                const int col = nc0 + wn * 32 + nt * 8 + (lane & 3) * 2;
                uint32_t h0, l0v, h1, l1v;
                pack_hilo(acc[mt][nt][0], acc[mt][nt][1], h0, l0v);
                pack_hilo(acc[mt][nt][2], acc[mt][nt][3], h1, l1v);
                *(uint32_t*)(C2h + (size_t)row * ldc2 + col)       = h0;
                *(uint32_t*)(C2l + (size_t)row * ldc2 + col)       = l0v;
                *(uint32_t*)(C2h + (size_t)(row + 8) * ldc2 + col) = h1;
                *(uint32_t*)(C2l + (size_t)(row + 8) * ldc2 + col) = l1v;
            }
        }
        return;
    }
#pragma unroll
    for (int mt = 0; mt < 4; mt++) {
        const int row = m0 + wm * 64 + mt * 16 + (lane >> 2);
#pragma unroll
        for (int nt = 0; nt < 4; nt++) {
            const int col = n0 + wn * 32 + nt * 8 + (lane & 3) * 2;
            float2 v0 = make_float2(acc[mt][nt][0], acc[mt][nt][1]);
            float2 v1 = make_float2(acc[mt][nt][2], acc[mt][nt][3]);
            *(float2*)(C0 + (size_t)row * ldc0 + col)       = v0;
            *(float2*)(C0 + (size_t)(row + 8) * ldc0 + col) = v1;
        }
    }
}

// ---------------------------------------------------------------------------
// Flash attention via mma.sync (bf16 hi/lo x3), fp32 softmax (exp2), causal.
// CTA: 64 q-rows x 1 head, 4 warps, 96KB smem -> 2 CTAs/SM.
// 3-stage KV ring; Q parked in slot 2 until fragments are hoisted.
// ONE __syncthreads per tile. (R12 proven config, reverted from R13)
// ---------------------------------------------------------------------------
#define ABQ  64
#define ABKV 32
#define KVSTAGE 32768      // per-stage: KH 0, KL 8K, VH 16K, VL 24K
#define SKH 0
#define SKL 8192
#define SVH 16384
#define SVL 24576
#define AQH (2 * KVSTAGE)            // Q parked in slot 2
#define AQL (AQH + 16384)
#define ATTN_SMEM (3 * KVSTAGE)      // 96 KB

__global__ __launch_bounds__(128, 2) void attn_mma_kernel(
    const __nv_bfloat16* __restrict__ Qh, const __nv_bfloat16* __restrict__ Ql,
    const __nv_bfloat16* __restrict__ Kh, const __nv_bfloat16* __restrict__ Kl,
    const __nv_bfloat16* __restrict__ Vh, const __nv_bfloat16* __restrict__ Vl,
    __nv_bfloat16* __restrict__ AOh, __nv_bfloat16* __restrict__ AOl)
{
    extern __shared__ __align__(1024) char smem[];
    const uint32_t sbase = smem_u32(smem);
    const int tid  = threadIdx.x;
    const int lane = tid & 31;
    const int wq   = tid >> 5;                              // 0..3
    const int qb   = (int)gridDim.x - 1 - (int)blockIdx.x;  // big tiles first
    const int h    = blockIdx.y, b = blockIdx.z;
    const int g    = h / NREP;
    const int q0   = qb * ABQ;
    const int rowmin = q0 + wq * 16;
    const int lr8 = tid >> 4;      // 0..7 row within 8-row pass
    const int lc  = tid & 15;      // 16B chunk within 256B row

    // ---- Q tile into slot 2 (group: Q) ----
#pragma unroll
    for (int i = 0; i < 8; i++) {
        const int row = i * 8 + lr8;
        const uint32_t off = (uint32_t)(row * 256 + ((lc ^ (row & 7)) * 16));
        const size_t gp = ((size_t)(b * S_LEN + q0 + row) * NH + h) * HD + lc * 8;
        cp16(sbase + AQH + off, Qh + gp);
        cp16(sbase + AQL + off, Ql + gp);
    }
    cp_commit();

    auto issue_kv = [&](int s, int k0) {
        const uint32_t st = sbase + s * KVSTAGE;
#pragma unroll
        for (int i = 0; i < 4; i++) {
            const int row = i * 8 + lr8;
            const uint32_t off = (uint32_t)(row * 256 + ((lc ^ (row & 7)) * 16));
            const size_t gp = ((size_t)(b * S_LEN + k0 + row) * NKV + g) * HD + lc * 8;
            cp16(st + SKH + off, Kh + gp);
            cp16(st + SKL + off, Kl + gp);
            cp16(st + SVH + off, Vh + gp);
            cp16(st + SVL + off, Vl + gp);
        }
        cp_commit();
    };
    const int ntile = 2 * qb + 2;   // always >= 2
    issue_kv(0, 0);                 // group: KV0
    issue_kv(1, ABKV);              // group: KV1

    // ---- hoist Q fragments (tile-invariant); slot 2 is free afterwards ----
    cp_wait<2>();    // Q group complete (KV0/KV1 may still be in flight)
    __syncthreads();
    uint32_t aqh_r[8][4], aql_r[8][4];
#pragma unroll
    for (int kt = 0; kt < 8; kt++) {
        ldm_x4_256(aqh_r[kt], sbase + AQH, wq * 16, kt * 2);
        ldm_x4_256(aql_r[kt], sbase + AQL, wq * 16, kt * 2);
    }

    float out[16][4];
#pragma unroll
    for (int i = 0; i < 16; i++)
#pragma unroll
        for (int j = 0; j < 4; j++) out[i][j] = 0.0f;
    float m0 = -1e30f, m1 = -1e30f, l0 = 0.0f, l1 = 0.0f;
    const float scl2 = 0.08838834764831845f * 1.4426950408889634f;  // /sqrt(128)*log2(e)

    for (int kb = 0; kb < ntile; kb++) {
        const int s = kb % 3;
        const int k0 = kb * ABKV;
        if (kb + 1 < ntile) cp_wait<1>();
        else                cp_wait<0>();
        __syncthreads();

        if (k0 <= rowmin + 15) {   // else tile fully masked for this warp
            const uint32_t stK = sbase + s * KVSTAGE;

            // ---- S = Q K^T  (16 x 32 x 128) ----
            float sc[4][4];
#pragma unroll
            for (int nt = 0; nt < 4; nt++)
#pragma unroll
                for (int j = 0; j < 4; j++) sc[nt][j] = 0.0f;
#pragma unroll
            for (int kt = 0; kt < 8; kt++) {
#pragma unroll
                for (int bp = 0; bp < 2; bp++) {
                    uint32_t bkh[4], bkl[4];
                    ldm_x4_256(bkh, stK + SKH, bp * 16, kt * 2);
                    ldm_x4_256(bkl, stK + SKL, bp * 16, kt * 2);
#pragma unroll
                    for (int o = 0; o < 2; o++) {
                        const int nt = bp * 2 + o;
                        mma_bf16(sc[nt], aqh_r[kt], bkh[o], bkh[o + 2]);
                        mma_bf16(sc[nt], aqh_r[kt], bkl[o], bkl[o + 2]);
                        mma_bf16(sc[nt], aql_r[kt], bkh[o], bkh[o + 2]);
                    }
                }
            }

            // ---- scale + causal mask + online softmax (exp2 domain) ----
            const int r0g = rowmin + (lane >> 2);
            const bool domask = (k0 + ABKV - 1) > rowmin;
            float mx0 = -1e30f, mx1 = -1e30f;
#pragma unroll
            for (int nt = 0; nt < 4; nt++) {
#pragma unroll
                for (int j = 0; j < 4; j++) {
                    float v = sc[nt][j] * scl2;
                    if (domask) {
                        int cg = k0 + nt * 8 + (lane & 3) * 2 + (j & 1);
                        int rg = r0g + ((j >> 1) << 3);
                        if (cg > rg) v = -1e30f;
                    }
                    sc[nt][j] = v;
                }
                mx0 = fmaxf(mx0, fmaxf(sc[nt][0], sc[nt][1]));
                mx1 = fmaxf(mx1, fmaxf(sc[nt][2], sc[nt][3]));
            }
            mx0 = fmaxf(mx0, __shfl_xor_sync(0xffffffffu, mx0, 1));
            mx0 = fmaxf(mx0, __shfl_xor_sync(0xffffffffu, mx0, 2));
            mx1 = fmaxf(mx1, __shfl_xor_sync(0xffffffffu, mx1, 1));
            mx1 = fmaxf(mx1, __shfl_xor_sync(0xffffffffu, mx1, 2));
            const float mn0 = fmaxf(m0, mx0), mn1 = fmaxf(m1, mx1);
            const float a0 = exp2f(m0 - mn0), a1 = exp2f(m1 - mn1);
            m0 = mn0; m1 = mn1;
            float ps0 = 0.0f, ps1 = 0.0f;
#pragma unroll
            for (int nt = 0; nt < 4; nt++) {
                sc[nt][0] = exp2f(sc[nt][0] - mn0); ps0 += sc[nt][0];
                sc[nt][1] = exp2f(sc[nt][1] - mn0); ps0 += sc[nt][1];
                sc[nt][2] = exp2f(sc[nt][2] - mn1); ps1 += sc[nt][2];
                sc[nt][3] = exp2f(sc[nt][3] - mn1); ps1 += sc[nt][3];
            }
            l0 = l0 * a0 + ps0;
            l1 = l1 * a1 + ps1;
#pragma unroll
            for (int dt = 0; dt < 16; dt++) {
                out[dt][0] *= a0; out[dt][1] *= a0;
                out[dt][2] *= a1; out[dt][3] *= a1;
            }

            // ---- O += P V  (16 x 128 x 32) ----
#pragma unroll
            for (int ktp = 0; ktp < 2; ktp++) {
                uint32_t aph[4], apl[4];
                const int t0 = ktp * 2, t1 = t0 + 1;
                pack_hilo(sc[t0][0], sc[t0][1], aph[0], apl[0]);
                pack_hilo(sc[t0][2], sc[t0][3], aph[1], apl[1]);
                pack_hilo(sc[t1][0], sc[t1][1], aph[2], apl[2]);
                pack_hilo(sc[t1][2], sc[t1][3], aph[3], apl[3]);
#pragma unroll
                for (int dt = 0; dt < 8; dt++) {
                    uint32_t bvh[4], bvl[4];
                    ldm_x4t_256(bvh, stK + SVH, ktp * 16, dt * 2);
                    ldm_x4t_256(bvl, stK + SVL, ktp * 16, dt * 2);
                    mma_bf16(out[dt * 2],     aph, bvh[0], bvh[1]);
                    mma_bf16(out[dt * 2],     aph, bvl[0], bvl[1]);
                    mma_bf16(out[dt * 2],     apl, bvh[0], bvh[1]);
                    mma_bf16(out[dt * 2 + 1], aph, bvh[2], bvh[3]);
                    mma_bf16(out[dt * 2 + 1], aph, bvl[2], bvl[3]);
                    mma_bf16(out[dt * 2 + 1], apl, bvh[2], bvh[3]);
                }
            }
        }

        if (kb + 2 < ntile) issue_kv((kb + 2) % 3, (kb + 2) * ABKV);
    }

    // ---- finalize: write bf16 hi/lo directly (feeds O-projection GEMM) ----
    l0 += __shfl_xor_sync(0xffffffffu, l0, 1);
    l0 += __shfl_xor_sync(0xffffffffu, l0, 2);
    l1 += __shfl_xor_sync(0xffffffffu, l1, 1);
    l1 += __shfl_xor_sync(0xffffffffu, l1, 2);
    const float i0 = 1.0f / l0, i1 = 1.0f / l1;
    const int r0g = rowmin + (lane >> 2);
    const size_t base0 = ((size_t)(b * S_LEN + r0g) * NH + h) * HD;
    const size_t base1 = base0 + (size_t)8 * NH * HD;
#pragma unroll
    for (int dt = 0; dt < 16; dt++) {
        const int col = dt * 8 + (lane & 3) * 2;
        uint32_t h0, l0p, h1, l1p;
        pack_hilo(out[dt][0] * i0, out[dt][1] * i0, h0, l0p);
        pack_hilo(out[dt][2] * i1, out[dt][3] * i1, h1, l1p);
        *(uint32_t*)(AOh + base0 + col) = h0;
        *(uint32_t*)(AOl + base0 + col) = l0p;
        *(uint32_t*)(AOh + base1 + col) = h1;
        *(uint32_t*)(AOl + base1 + col) = l1p;
    }
}

// ---------------------------------------------------------------------------
// Launch
// ---------------------------------------------------------------------------
extern "C" void kernel_launch(void* const* d_in, const int* in_sizes, int n_in,
                              void* d_out, int out_size)
{
    const float* hs = (const float*)d_in[0];
    const float* wq = (const float*)d_in[1];
    const float* wk = (const float*)d_in[2];
    const float* wv = (const float*)d_in[3];
    const float* wo = (const float*)d_in[4];
    const int*  pos = (const int*)  d_in[6];
    float*      out = (float*)d_out;

    __nv_bfloat16 *hsh, *hsl, *wh, *wl, *woh, *wol, *aoh, *aol;
    __nv_bfloat16 *qh, *ql, *kh, *kl, *vh, *vl;
    cudaGetSymbolAddress((void**)&hsh, g_hs_h); cudaGetSymbolAddress((void**)&hsl, g_hs_l);
    cudaGetSymbolAddress((void**)&wh,  g_w_h);  cudaGetSymbolAddress((void**)&wl,  g_w_l);
    cudaGetSymbolAddress((void**)&woh, g_wo_h); cudaGetSymbolAddress((void**)&wol, g_wo_l);
    cudaGetSymbolAddress((void**)&aoh, g_ao_h); cudaGetSymbolAddress((void**)&aol, g_ao_l);
    cudaGetSymbolAddress((void**)&qh,  g_q_h);  cudaGetSymbolAddress((void**)&ql,  g_q_l);
    cudaGetSymbolAddress((void**)&kh,  g_k_h);  cudaGetSymbolAddress((void**)&kl,  g_k_l);
    cudaGetSymbolAddress((void**)&vh,  g_v_h);  cudaGetSymbolAddress((void**)&vl,  g_v_l);

    cudaFuncSetAttribute(gemm_mma_kernel, cudaFuncAttributeMaxDynamicSharedMemorySize, GEMM_SMEM);
    cudaFuncSetAttribute(attn_mma_kernel, cudaFuncAttributeMaxDynamicSharedMemorySize, ATTN_SMEM);

    // One merged conversion launch (wq/wk row-permuted for local RoPE pairs).
    cvt_all_kernel<<<CVT_BLOCKS, 256>>>(
        (const float4*)hs, (uint2*)hsh, (uint2*)hsl,
        (const float4*)wq, (uint2*)wh,              (uint2*)wl,
        (const float4*)wk, (uint2*)(wh + 16777216u), (uint2*)(wl + 16777216u),
        (const float4*)wv, (uint2*)(wh + 20971520u), (uint2*)(wl + 20971520u),
        (const float4*)wo, (uint2*)woh, (uint2*)wol);

    // Merged QKV projection: N = 6144.
    // q/k tiles -> RoPE epilogue writing qh/ql/kh/kl; v tiles -> bf16 hi/lo.
    gemm_mma_kernel<<<dim3(6144 / TBN, MROWS / TBM), 128, GEMM_SMEM>>>(
        hsh, hsl, wh, wl,
        pos, qh, ql, kh, kl,
        nullptr, vh, vl,
        4096, 5120, 0, NKV * HD,
        MROWS, 6144, HID);

    // Causal flash attention (mma.sync, 2 CTAs/SM, 3-stage ring, 1 sync/tile)
    attn_mma_kernel<<<dim3(S_LEN / ABQ, NH, B_SZ), 128, ATTN_SMEM>>>(
        qh, ql, kh, kl, vh, vl, aoh, aol);

    // Output projection (plain fp32 epilogue)
    gemm_mma_kernel<<<dim3(HID / TBN, MROWS / TBM), 128, GEMM_SMEM>>>(
        aoh, aol, woh, wol,
        nullptr, nullptr, nullptr, nullptr, nullptr,
        out, nullptr, nullptr,
        HID, HID, HID, 0,
        MROWS, HID, NH * HD);
}